// round 9
// baseline (speedup 1.0000x reference)
#include <cuda_runtime.h>

#define T 3
#define B 100000
#define D 128
#define NEG_SLOPE 0.01f

// One warp per (t, b). Lane l owns elements [4l, 4l+4) of D.
// R2 shape (32 regs, occ ~85%) + streaming cache hints: every HBM line is
// single-use, so .cs marks it evict-first in L1/L2.
__global__ void __launch_bounds__(256, 8)
attconv_kernel(const float* __restrict__ h_center,
               const float* __restrict__ h_neigh,
               const float* __restrict__ att_w,
               const float* __restrict__ att_b,
               float* __restrict__ out)
{
    const int warp = threadIdx.x >> 5;
    const int lane = threadIdx.x & 31;
    const int slot = blockIdx.x * (blockDim.x >> 5) + warp;
    if (slot >= T * B) return;
    const int t = slot / B;
    const int b = slot - t * B;

    // Front-batch the 4 streaming loads (MLP=4 per warp; occupancy supplies the rest).
    const size_t cbase   = ((size_t)t * B + b) * D + lane * 4;
    const size_t nstride = (size_t)B * D;
    const size_t nbase   = ((size_t)t * T) * nstride + (size_t)b * D + lane * 4;

    const float4 c4 = __ldcs(reinterpret_cast<const float4*>(h_center + cbase));
    const float4 v0 = __ldcs(reinterpret_cast<const float4*>(h_neigh + nbase));
    const float4 v1 = __ldcs(reinterpret_cast<const float4*>(h_neigh + nbase + nstride));
    const float4 v2 = __ldcs(reinterpret_cast<const float4*>(h_neigh + nbase + 2 * nstride));

    // Per-t weights: L2-resident, heavily reused -> default caching.
    const float4 wh = *reinterpret_cast<const float4*>(att_w + (size_t)t * 2 * D + lane * 4);
    const float4 we = *reinterpret_cast<const float4*>(att_w + (size_t)t * 2 * D + D + lane * 4);
    const float bias = att_b[t];

    // Per-lane partial dot products (5 chains).
    float se0 = v0.x * we.x + v0.y * we.y + v0.z * we.z + v0.w * we.w;
    float se1 = v1.x * we.x + v1.y * we.y + v1.z * we.z + v1.w * we.w;
    float se2 = v2.x * we.x + v2.y * we.y + v2.z * we.z + v2.w * we.w;
    float sec = c4.x * we.x + c4.y * we.y + c4.z * we.z + c4.w * we.w;
    float sh  = c4.x * wh.x + c4.y * wh.y + c4.z * wh.z + c4.w * wh.w;

    // Butterfly warp reductions -> all lanes hold full sums.
    #pragma unroll
    for (int off = 16; off > 0; off >>= 1) {
        se0 += __shfl_xor_sync(0xFFFFFFFFu, se0, off);
        se1 += __shfl_xor_sync(0xFFFFFFFFu, se1, off);
        se2 += __shfl_xor_sync(0xFFFFFFFFu, se2, off);
        sec += __shfl_xor_sync(0xFFFFFFFFu, sec, off);
        sh  += __shfl_xor_sync(0xFFFFFFFFu, sh,  off);
    }

    // scores = score_e + score_h + bias, leaky relu, 4-way softmax.
    const float shb = sh + bias;
    float s0 = se0 + shb;
    float s1 = se1 + shb;
    float s2 = se2 + shb;
    float s3 = sec + shb;        // center occupies the last concat slot

    s0 = (s0 >= 0.f) ? s0 : NEG_SLOPE * s0;
    s1 = (s1 >= 0.f) ? s1 : NEG_SLOPE * s1;
    s2 = (s2 >= 0.f) ? s2 : NEG_SLOPE * s2;
    s3 = (s3 >= 0.f) ? s3 : NEG_SLOPE * s3;

    float m = fmaxf(fmaxf(s0, s1), fmaxf(s2, s3));
    float e0 = __expf(s0 - m);
    float e1 = __expf(s1 - m);
    float e2 = __expf(s2 - m);
    float e3 = __expf(s3 - m);
    float inv = 1.0f / (e0 + e1 + e2 + e3);
    e0 *= inv; e1 *= inv; e2 *= inv; e3 *= inv;

    // Weighted blend of the 4 vectors; streaming store (write-once).
    float4 o;
    o.x = e0 * v0.x + e1 * v1.x + e2 * v2.x + e3 * c4.x;
    o.y = e0 * v0.y + e1 * v1.y + e2 * v2.y + e3 * c4.y;
    o.z = e0 * v0.z + e1 * v1.z + e2 * v2.z + e3 * c4.z;
    o.w = e0 * v0.w + e1 * v1.w + e2 * v2.w + e3 * c4.w;
    __stcs(reinterpret_cast<float4*>(out + cbase), o);
}

extern "C" void kernel_launch(void* const* d_in, const int* in_sizes, int n_in,
                              void* d_out, int out_size)
{
    const float* h_center = (const float*)d_in[0];
    const float* h_neigh  = (const float*)d_in[1];
    const float* att_w    = (const float*)d_in[2];
    const float* att_b    = (const float*)d_in[3];
    float* out = (float*)d_out;

    const int warps_per_block = 8;                   // 256 threads
    const int total_warps = T * B;                   // 300000 (t,b) pairs
    dim3 block(32 * warps_per_block);
    dim3 grid((total_warps + warps_per_block - 1) / warps_per_block);
    attconv_kernel<<<grid, block>>>(h_center, h_neigh, att_w, att_b, out);
}

// round 10
// speedup vs baseline: 1.0009x; 1.0009x over previous
#include <cuda_runtime.h>

#define T 3
#define B 100000
#define D 128
#define NEG_SLOPE 0.01f

// FINAL (converged at HBM ceiling — 3 variants all measure 110.4–110.8 µs @ ~88% DRAM).
// One warp per (t, b). Lane l owns elements [4l, 4l+4) of D: every vector access
// is one coalesced 512B LDG.128/STG.128 warp transaction. Occupancy (85%) supplies
// chip-wide MLP; .cs marks the one-touch stream evict-first (neutral, non-harmful).
__global__ void __launch_bounds__(256, 8)
attconv_kernel(const float* __restrict__ h_center,
               const float* __restrict__ h_neigh,
               const float* __restrict__ att_w,
               const float* __restrict__ att_b,
               float* __restrict__ out)
{
    const int warp = threadIdx.x >> 5;
    const int lane = threadIdx.x & 31;
    const int slot = blockIdx.x * (blockDim.x >> 5) + warp;
    if (slot >= T * B) return;
    const int t = slot / B;
    const int b = slot - t * B;

    // Front-batch the 4 streaming loads.
    const size_t cbase   = ((size_t)t * B + b) * D + lane * 4;
    const size_t nstride = (size_t)B * D;
    const size_t nbase   = ((size_t)t * T) * nstride + (size_t)b * D + lane * 4;

    const float4 c4 = __ldcs(reinterpret_cast<const float4*>(h_center + cbase));
    const float4 v0 = __ldcs(reinterpret_cast<const float4*>(h_neigh + nbase));
    const float4 v1 = __ldcs(reinterpret_cast<const float4*>(h_neigh + nbase + nstride));
    const float4 v2 = __ldcs(reinterpret_cast<const float4*>(h_neigh + nbase + 2 * nstride));

    // Per-t weights: L2-resident, heavily reused -> default caching.
    const float4 wh = *reinterpret_cast<const float4*>(att_w + (size_t)t * 2 * D + lane * 4);
    const float4 we = *reinterpret_cast<const float4*>(att_w + (size_t)t * 2 * D + D + lane * 4);
    const float bias = att_b[t];

    // Per-lane partial dot products (5 chains).
    float se0 = v0.x * we.x + v0.y * we.y + v0.z * we.z + v0.w * we.w;
    float se1 = v1.x * we.x + v1.y * we.y + v1.z * we.z + v1.w * we.w;
    float se2 = v2.x * we.x + v2.y * we.y + v2.z * we.z + v2.w * we.w;
    float sec = c4.x * we.x + c4.y * we.y + c4.z * we.z + c4.w * we.w;
    float sh  = c4.x * wh.x + c4.y * wh.y + c4.z * wh.z + c4.w * wh.w;

    // Butterfly warp reductions -> all lanes hold full sums.
    #pragma unroll
    for (int off = 16; off > 0; off >>= 1) {
        se0 += __shfl_xor_sync(0xFFFFFFFFu, se0, off);
        se1 += __shfl_xor_sync(0xFFFFFFFFu, se1, off);
        se2 += __shfl_xor_sync(0xFFFFFFFFu, se2, off);
        sec += __shfl_xor_sync(0xFFFFFFFFu, sec, off);
        sh  += __shfl_xor_sync(0xFFFFFFFFu, sh,  off);
    }

    // scores = score_e + score_h + bias, leaky relu, 4-way softmax.
    const float shb = sh + bias;
    float s0 = se0 + shb;
    float s1 = se1 + shb;
    float s2 = se2 + shb;
    float s3 = sec + shb;        // center occupies the last concat slot

    s0 = (s0 >= 0.f) ? s0 : NEG_SLOPE * s0;
    s1 = (s1 >= 0.f) ? s1 : NEG_SLOPE * s1;
    s2 = (s2 >= 0.f) ? s2 : NEG_SLOPE * s2;
    s3 = (s3 >= 0.f) ? s3 : NEG_SLOPE * s3;

    float m = fmaxf(fmaxf(s0, s1), fmaxf(s2, s3));
    float e0 = __expf(s0 - m);
    float e1 = __expf(s1 - m);
    float e2 = __expf(s2 - m);
    float e3 = __expf(s3 - m);
    float inv = 1.0f / (e0 + e1 + e2 + e3);
    e0 *= inv; e1 *= inv; e2 *= inv; e3 *= inv;

    // Weighted blend of the 4 vectors; streaming store (write-once).
    float4 o;
    o.x = e0 * v0.x + e1 * v1.x + e2 * v2.x + e3 * c4.x;
    o.y = e0 * v0.y + e1 * v1.y + e2 * v2.y + e3 * c4.y;
    o.z = e0 * v0.z + e1 * v1.z + e2 * v2.z + e3 * c4.z;
    o.w = e0 * v0.w + e1 * v1.w + e2 * v2.w + e3 * c4.w;
    __stcs(reinterpret_cast<float4*>(out + cbase), o);
}

extern "C" void kernel_launch(void* const* d_in, const int* in_sizes, int n_in,
                              void* d_out, int out_size)
{
    const float* h_center = (const float*)d_in[0];
    const float* h_neigh  = (const float*)d_in[1];
    const float* att_w    = (const float*)d_in[2];
    const float* att_b    = (const float*)d_in[3];
    float* out = (float*)d_out;

    const int warps_per_block = 8;                   // 256 threads
    const int total_warps = T * B;                   // 300000 (t,b) pairs
    dim3 block(32 * warps_per_block);
    dim3 grid((total_warps + warps_per_block - 1) / warps_per_block);
    attconv_kernel<<<grid, block>>>(h_center, h_neigh, att_w, att_b, out);
}

// round 11
// speedup vs baseline: 1.0079x; 1.0070x over previous
#include <cuda_runtime.h>

#define T 3
#define B 100000
#define D 128
#define NEG_SLOPE 0.01f

// Converged-at-ceiling kernel (110.4-110.8 us @ ~88% DRAM across 4 runs / 3 shapes).
// This round: identical per-warp code, 16 warps/block (halves CTA count; zero-barrier
// kernel so CTA size is free). One warp per (t, b); lane l owns D-slice [4l, 4l+4):
// every vector access is one coalesced 512B LDG.128/STG.128 warp transaction.
__global__ void __launch_bounds__(512, 4)
attconv_kernel(const float* __restrict__ h_center,
               const float* __restrict__ h_neigh,
               const float* __restrict__ att_w,
               const float* __restrict__ att_b,
               float* __restrict__ out)
{
    const int warp = threadIdx.x >> 5;
    const int lane = threadIdx.x & 31;
    const int slot = blockIdx.x * (blockDim.x >> 5) + warp;
    if (slot >= T * B) return;
    const int t = slot / B;
    const int b = slot - t * B;

    // Front-batch the 4 streaming loads (.cs: one-touch data, evict-first).
    const size_t cbase   = ((size_t)t * B + b) * D + lane * 4;
    const size_t nstride = (size_t)B * D;
    const size_t nbase   = ((size_t)t * T) * nstride + (size_t)b * D + lane * 4;

    const float4 c4 = __ldcs(reinterpret_cast<const float4*>(h_center + cbase));
    const float4 v0 = __ldcs(reinterpret_cast<const float4*>(h_neigh + nbase));
    const float4 v1 = __ldcs(reinterpret_cast<const float4*>(h_neigh + nbase + nstride));
    const float4 v2 = __ldcs(reinterpret_cast<const float4*>(h_neigh + nbase + 2 * nstride));

    // Per-t weights: L2-resident, heavily reused -> default caching.
    const float4 wh = *reinterpret_cast<const float4*>(att_w + (size_t)t * 2 * D + lane * 4);
    const float4 we = *reinterpret_cast<const float4*>(att_w + (size_t)t * 2 * D + D + lane * 4);
    const float bias = att_b[t];

    // Per-lane partial dot products (5 chains).
    float se0 = v0.x * we.x + v0.y * we.y + v0.z * we.z + v0.w * we.w;
    float se1 = v1.x * we.x + v1.y * we.y + v1.z * we.z + v1.w * we.w;
    float se2 = v2.x * we.x + v2.y * we.y + v2.z * we.z + v2.w * we.w;
    float sec = c4.x * we.x + c4.y * we.y + c4.z * we.z + c4.w * we.w;
    float sh  = c4.x * wh.x + c4.y * wh.y + c4.z * wh.z + c4.w * wh.w;

    // Butterfly warp reductions -> all lanes hold full sums.
    #pragma unroll
    for (int off = 16; off > 0; off >>= 1) {
        se0 += __shfl_xor_sync(0xFFFFFFFFu, se0, off);
        se1 += __shfl_xor_sync(0xFFFFFFFFu, se1, off);
        se2 += __shfl_xor_sync(0xFFFFFFFFu, se2, off);
        sec += __shfl_xor_sync(0xFFFFFFFFu, sec, off);
        sh  += __shfl_xor_sync(0xFFFFFFFFu, sh,  off);
    }

    // scores = score_e + score_h + bias, leaky relu, 4-way softmax.
    const float shb = sh + bias;
    float s0 = se0 + shb;
    float s1 = se1 + shb;
    float s2 = se2 + shb;
    float s3 = sec + shb;        // center occupies the last concat slot

    s0 = (s0 >= 0.f) ? s0 : NEG_SLOPE * s0;
    s1 = (s1 >= 0.f) ? s1 : NEG_SLOPE * s1;
    s2 = (s2 >= 0.f) ? s2 : NEG_SLOPE * s2;
    s3 = (s3 >= 0.f) ? s3 : NEG_SLOPE * s3;

    float m = fmaxf(fmaxf(s0, s1), fmaxf(s2, s3));
    float e0 = __expf(s0 - m);
    float e1 = __expf(s1 - m);
    float e2 = __expf(s2 - m);
    float e3 = __expf(s3 - m);
    float inv = 1.0f / (e0 + e1 + e2 + e3);
    e0 *= inv; e1 *= inv; e2 *= inv; e3 *= inv;

    // Weighted blend of the 4 vectors; streaming store (write-once).
    float4 o;
    o.x = e0 * v0.x + e1 * v1.x + e2 * v2.x + e3 * c4.x;
    o.y = e0 * v0.y + e1 * v1.y + e2 * v2.y + e3 * c4.y;
    o.z = e0 * v0.z + e1 * v1.z + e2 * v2.z + e3 * c4.z;
    o.w = e0 * v0.w + e1 * v1.w + e2 * v2.w + e3 * c4.w;
    __stcs(reinterpret_cast<float4*>(out + cbase), o);
}

extern "C" void kernel_launch(void* const* d_in, const int* in_sizes, int n_in,
                              void* d_out, int out_size)
{
    const float* h_center = (const float*)d_in[0];
    const float* h_neigh  = (const float*)d_in[1];
    const float* att_w    = (const float*)d_in[2];
    const float* att_b    = (const float*)d_in[3];
    float* out = (float*)d_out;

    const int warps_per_block = 16;                  // 512 threads
    const int total_warps = T * B;                   // 300000 (t,b) pairs
    dim3 block(32 * warps_per_block);
    dim3 grid((total_warps + warps_per_block - 1) / warps_per_block);
    attconv_kernel<<<grid, block>>>(h_center, h_neigh, att_w, att_b, out);
}